// round 1
// baseline (speedup 1.0000x reference)
#include <cuda_runtime.h>
#include <cuda_bf16.h>

// Problem constants (validated against in_sizes at launch)
#define NMAX 50000
#define DDIM 256

// Scratch (device globals — no allocations allowed)
__device__ float g_h[NMAX * DDIM];    // h = A @ W  (per layer)
__device__ float g_agg[NMAX * DDIM];  // scatter accumulator
__device__ float g_z[NMAX * DDIM];    // layer-1 output (input to layer 2)
__device__ float g_deg[NMAX];         // degree, then overwritten with rsqrt(deg)

// ---------------------------------------------------------------------------
// degree kernels
// ---------------------------------------------------------------------------
__global__ void deg_init_kernel(int N) {
    int i = blockIdx.x * blockDim.x + threadIdx.x;
    if (i < N) g_deg[i] = 1.0f;  // self-loop weight
}

__global__ void deg_acc_kernel(const int* __restrict__ col,
                               const float* __restrict__ ew, int E) {
    int e = blockIdx.x * blockDim.x + threadIdx.x;
    if (e < E) atomicAdd(&g_deg[col[e]], ew[e]);
}

__global__ void dinv_kernel(int N) {
    int i = blockIdx.x * blockDim.x + threadIdx.x;
    if (i < N) g_deg[i] = rsqrtf(g_deg[i]);  // deg >= 1 always
}

// ---------------------------------------------------------------------------
// zero the aggregation buffer (float4 grid-stride)
// ---------------------------------------------------------------------------
__global__ void zero_agg_kernel(int n4) {
    int i = blockIdx.x * blockDim.x + threadIdx.x;
    if (i < n4) ((float4*)g_agg)[i] = make_float4(0.f, 0.f, 0.f, 0.f);
}

// ---------------------------------------------------------------------------
// GEMM: C[M,256] = A[M,256] @ W[256,256], FP32, 64x64x16 tile, 4x4/thread
// layer==0: A = x (external), layer==1: A = g_z.  C = g_h always.
// ---------------------------------------------------------------------------
#define BM 64
#define BN 64
#define BK 16

__global__ __launch_bounds__(256) void gemm_kernel(const float* __restrict__ x_in,
                                                   const float* __restrict__ W,
                                                   int M, int layer) {
    const float* __restrict__ A = (layer == 0) ? x_in : (const float*)g_z;
    float* __restrict__ C = g_h;

    __shared__ float As[BK][BM];
    __shared__ float Bs[BK][BN + 4];  // pad to soften bank conflicts

    int bx = blockIdx.x;   // N tile: 0..3
    int by = blockIdx.y;   // M tile
    int tid = threadIdx.x;
    int tx = tid & 15;     // N direction (16)
    int ty = tid >> 4;     // M direction (16)

    int rowBase = by * BM;
    int colBase = bx * BN;

    float acc[4][4];
#pragma unroll
    for (int i = 0; i < 4; i++)
#pragma unroll
        for (int j = 0; j < 4; j++) acc[i][j] = 0.f;

    for (int k0 = 0; k0 < DDIM; k0 += BK) {
        // load A tile (BM x BK), store transposed: As[k][m]
#pragma unroll
        for (int i = 0; i < 4; i++) {
            int idx = tid + i * 256;      // 0..1023
            int m = idx >> 4;             // /BK
            int kk = idx & 15;            // %BK
            int gm = rowBase + m;
            As[kk][m] = (gm < M) ? A[(size_t)gm * DDIM + k0 + kk] : 0.f;
        }
        // load B tile (BK x BN)
#pragma unroll
        for (int i = 0; i < 4; i++) {
            int idx = tid + i * 256;
            int kk = idx >> 6;            // /BN
            int n = idx & 63;             // %BN
            Bs[kk][n] = W[(size_t)(k0 + kk) * DDIM + colBase + n];
        }
        __syncthreads();

#pragma unroll
        for (int kk = 0; kk < BK; kk++) {
            float a[4], b[4];
#pragma unroll
            for (int i = 0; i < 4; i++) a[i] = As[kk][ty * 4 + i];
#pragma unroll
            for (int j = 0; j < 4; j++) b[j] = Bs[kk][tx * 4 + j];
#pragma unroll
            for (int i = 0; i < 4; i++)
#pragma unroll
                for (int j = 0; j < 4; j++) acc[i][j] += a[i] * b[j];
        }
        __syncthreads();
    }

#pragma unroll
    for (int i = 0; i < 4; i++) {
        int m = rowBase + ty * 4 + i;
        if (m < M) {
            float4 v = make_float4(acc[i][0], acc[i][1], acc[i][2], acc[i][3]);
            *(float4*)&C[(size_t)m * DDIM + colBase + tx * 4] = v;
        }
    }
}

// ---------------------------------------------------------------------------
// Edge scatter: agg[col] += norm * h[row], norm = dinv[row]*ew*dinv[col]
// 64 threads per edge (float4 over D=256), 4 edges per 256-thread block.
// ---------------------------------------------------------------------------
__global__ __launch_bounds__(256) void scatter_kernel(const int* __restrict__ row,
                                                      const int* __restrict__ col,
                                                      const float* __restrict__ ew,
                                                      int E) {
    int e = blockIdx.x * 4 + (threadIdx.x >> 6);
    int lane = threadIdx.x & 63;
    if (e >= E) return;

    int r = row[e];
    int c = col[e];
    float nrm = g_deg[r] * ew[e] * g_deg[c];

    float4 v = ((const float4*)(g_h + (size_t)r * DDIM))[lane];
    float* ap = g_agg + (size_t)c * DDIM + lane * 4;
    atomicAdd(ap + 0, nrm * v.x);
    atomicAdd(ap + 1, nrm * v.y);
    atomicAdd(ap + 2, nrm * v.z);
    atomicAdd(ap + 3, nrm * v.w);
}

// ---------------------------------------------------------------------------
// Epilogue: out = relu(agg + dinv^2 * h + b)
// layer==0 -> write g_z, layer==1 -> write d_out
// ---------------------------------------------------------------------------
__global__ void epilogue_kernel(const float* __restrict__ b, float* __restrict__ out,
                                int N, int layer) {
    int idx = blockIdx.x * blockDim.x + threadIdx.x;  // over N*64 float4s
    if (idx >= N * (DDIM / 4)) return;
    int node = idx >> 6;
    int l = idx & 63;

    float di = g_deg[node];
    float s = di * di;
    float4 a = ((const float4*)g_agg)[idx];
    float4 h = ((const float4*)g_h)[idx];
    float4 bb = ((const float4*)b)[l];

    float4 o;
    o.x = fmaxf(a.x + s * h.x + bb.x, 0.f);
    o.y = fmaxf(a.y + s * h.y + bb.y, 0.f);
    o.z = fmaxf(a.z + s * h.z + bb.z, 0.f);
    o.w = fmaxf(a.w + s * h.w + bb.w, 0.f);

    float4* dst = (layer == 0) ? (float4*)g_z : (float4*)out;
    dst[idx] = o;
}

// ---------------------------------------------------------------------------
// launch
// ---------------------------------------------------------------------------
extern "C" void kernel_launch(void* const* d_in, const int* in_sizes, int n_in,
                              void* d_out, int out_size) {
    const float* x  = (const float*)d_in[0];
    const int*   ei = (const int*)d_in[1];
    const float* ew = (const float*)d_in[2];
    const float* W1 = (const float*)d_in[3];
    const float* b1 = (const float*)d_in[4];
    const float* W2 = (const float*)d_in[5];
    const float* b2 = (const float*)d_in[6];
    float* out = (float*)d_out;

    int N = in_sizes[0] / DDIM;   // 50000
    int E = in_sizes[2];          // 800000
    const int* row = ei;
    const int* col = ei + E;

    int n4 = N * (DDIM / 4);

    // degree / normalization (shared by both layers)
    deg_init_kernel<<<(N + 255) / 256, 256>>>(N);
    deg_acc_kernel<<<(E + 255) / 256, 256>>>(col, ew, E);
    dinv_kernel<<<(N + 255) / 256, 256>>>(N);

    dim3 ggrid(DDIM / BN, (N + BM - 1) / BM);

    // ---- layer 1 ----
    zero_agg_kernel<<<(n4 + 255) / 256, 256>>>(n4);
    gemm_kernel<<<ggrid, 256>>>(x, W1, N, 0);
    scatter_kernel<<<(E + 3) / 4, 256>>>(row, col, ew, E);
    epilogue_kernel<<<(n4 + 255) / 256, 256>>>(b1, out, N, 0);

    // ---- layer 2 ----
    zero_agg_kernel<<<(n4 + 255) / 256, 256>>>(n4);
    gemm_kernel<<<ggrid, 256>>>(x, W2, N, 1);
    scatter_kernel<<<(E + 3) / 4, 256>>>(row, col, ew, E);
    epilogue_kernel<<<(n4 + 255) / 256, 256>>>(b2, out, N, 1);
}

// round 4
// speedup vs baseline: 1.1695x; 1.1695x over previous
#include <cuda_runtime.h>
#include <cuda_bf16.h>

#define NMAX 50000
#define DDIM 256

// Scratch (device globals — no allocations allowed)
__device__ __align__(256) float g_h[NMAX * DDIM];    // h = A @ W (per layer)
__device__ __align__(256) float g_agg[NMAX * DDIM];  // accumulator (init = dinv^2*h + b)
__device__ __align__(256) float g_z[NMAX * DDIM];    // layer-1 output
__device__ __align__(256) float g_deg[NMAX];         // degree -> rsqrt(deg)

// ---------------------------------------------------------------------------
// degree
// ---------------------------------------------------------------------------
__global__ void deg_init_kernel(int N) {
    int i = blockIdx.x * blockDim.x + threadIdx.x;
    if (i < N) g_deg[i] = 1.0f;  // self-loop weight
}

__global__ void deg_acc_kernel(const int* __restrict__ col,
                               const float* __restrict__ ew, int E) {
    int e = blockIdx.x * blockDim.x + threadIdx.x;
    if (e < E) atomicAdd(&g_deg[col[e]], ew[e]);
}

__global__ void dinv_kernel(int N) {
    int i = blockIdx.x * blockDim.x + threadIdx.x;
    if (i < N) g_deg[i] = rsqrtf(g_deg[i]);
}

// ---------------------------------------------------------------------------
// GEMM: g_h[M,256] = A[M,256] @ W[256,256], FP32
// 128x128x8 tile, 256 threads, 8x8 per thread (2x(4+4) split), reg prefetch.
// ---------------------------------------------------------------------------
#define BM 128
#define BN 128
#define BK 8

__global__ __launch_bounds__(256) void gemm_kernel(const float* __restrict__ x_in,
                                                   const float* __restrict__ W,
                                                   int M, int layer) {
    const float* __restrict__ A = (layer == 0) ? x_in : (const float*)g_z;

    __shared__ float As[BK][BM];
    __shared__ float Bs[BK][BN];

    int tid = threadIdx.x;
    int tx = tid & 15;   // 0..15 (N groups)
    int ty = tid >> 4;   // 0..15 (M groups)

    int rowBase = blockIdx.y * BM;
    int colBase = blockIdx.x * BN;

    int arow = tid >> 1;
    int acol = (tid & 1) * 4;
    int brow = tid >> 5;
    int bcol = (tid & 31) * 4;

    int gm = rowBase + arow;
    bool aok = (gm < M);

    float4 aReg = aok ? *(const float4*)&A[(size_t)gm * DDIM + acol]
                      : make_float4(0.f, 0.f, 0.f, 0.f);
    float4 bReg = *(const float4*)&W[(size_t)brow * DDIM + colBase + bcol];

    float acc[8][8];
#pragma unroll
    for (int i = 0; i < 8; i++)
#pragma unroll
        for (int j = 0; j < 8; j++) acc[i][j] = 0.f;

    float af[8], bf[8];

    for (int k0 = 0; k0 < DDIM; k0 += BK) {
        As[acol + 0][arow] = aReg.x;
        As[acol + 1][arow] = aReg.y;
        As[acol + 2][arow] = aReg.z;
        As[acol + 3][arow] = aReg.w;
        *(float4*)&Bs[brow][bcol] = bReg;
        __syncthreads();

        if (k0 + BK < DDIM) {
            aReg = aok ? *(const float4*)&A[(size_t)gm * DDIM + k0 + BK + acol]
                       : make_float4(0.f, 0.f, 0.f, 0.f);
            bReg = *(const float4*)&W[(size_t)(k0 + BK + brow) * DDIM + colBase + bcol];
        }

#pragma unroll
        for (int kk = 0; kk < BK; kk++) {
            *(float4*)&af[0] = *(const float4*)&As[kk][ty * 4];
            *(float4*)&af[4] = *(const float4*)&As[kk][ty * 4 + 64];
            *(float4*)&bf[0] = *(const float4*)&Bs[kk][tx * 4];
            *(float4*)&bf[4] = *(const float4*)&Bs[kk][tx * 4 + 64];
#pragma unroll
            for (int i = 0; i < 8; i++)
#pragma unroll
                for (int j = 0; j < 8; j++) acc[i][j] += af[i] * bf[j];
        }
        __syncthreads();
    }

#pragma unroll
    for (int ih = 0; ih < 2; ih++) {
#pragma unroll
        for (int i = 0; i < 4; i++) {
            int m = rowBase + ty * 4 + ih * 64 + i;
            if (m < M) {
                int r = ih * 4 + i;
                *(float4*)&g_h[(size_t)m * DDIM + colBase + tx * 4] =
                    make_float4(acc[r][0], acc[r][1], acc[r][2], acc[r][3]);
                *(float4*)&g_h[(size_t)m * DDIM + colBase + tx * 4 + 64] =
                    make_float4(acc[r][4], acc[r][5], acc[r][6], acc[r][7]);
            }
        }
    }
}

// ---------------------------------------------------------------------------
// agg init: agg = dinv^2 * h + b  (self-loop term + bias, replaces zeroing)
// ---------------------------------------------------------------------------
__global__ void init_agg_kernel(const float* __restrict__ b, int N) {
    int idx = blockIdx.x * blockDim.x + threadIdx.x;  // over N*64 float4s
    if (idx >= N * (DDIM / 4)) return;
    int node = idx >> 6;
    int l = idx & 63;

    float di = g_deg[node];
    float s = di * di;
    float4 h = ((const float4*)g_h)[idx];
    float4 bb = ((const float4*)b)[l];

    float4 o;
    o.x = fmaf(s, h.x, bb.x);
    o.y = fmaf(s, h.y, bb.y);
    o.z = fmaf(s, h.z, bb.z);
    o.w = fmaf(s, h.w, bb.w);
    ((float4*)g_agg)[idx] = o;
}

// ---------------------------------------------------------------------------
// Edge scatter: agg[col] += norm * h[row]  (scalar atomics — R1-proven path)
// 64 threads per edge, 4 edges per 256-thread block.
// ---------------------------------------------------------------------------
__global__ __launch_bounds__(256) void scatter_kernel(const int* __restrict__ row,
                                                      const int* __restrict__ col,
                                                      const float* __restrict__ ew,
                                                      int E) {
    int e = blockIdx.x * 4 + (threadIdx.x >> 6);
    int lane = threadIdx.x & 63;
    if (e >= E) return;

    int r = __ldg(&row[e]);
    int c = __ldg(&col[e]);
    float nrm = g_deg[r] * __ldg(&ew[e]) * g_deg[c];

    float4 v = ((const float4*)(g_h + (size_t)r * DDIM))[lane];
    float* ap = g_agg + (size_t)c * DDIM + lane * 4;
    atomicAdd(ap + 0, nrm * v.x);
    atomicAdd(ap + 1, nrm * v.y);
    atomicAdd(ap + 2, nrm * v.z);
    atomicAdd(ap + 3, nrm * v.w);
}

// ---------------------------------------------------------------------------
// ReLU: dst = max(agg, 0)
// ---------------------------------------------------------------------------
__global__ void relu_kernel(float* __restrict__ out, int N, int layer) {
    int idx = blockIdx.x * blockDim.x + threadIdx.x;
    if (idx >= N * (DDIM / 4)) return;
    float4 a = ((const float4*)g_agg)[idx];
    float4 o;
    o.x = fmaxf(a.x, 0.f);
    o.y = fmaxf(a.y, 0.f);
    o.z = fmaxf(a.z, 0.f);
    o.w = fmaxf(a.w, 0.f);
    float4* dst = (layer == 0) ? (float4*)g_z : (float4*)out;
    dst[idx] = o;
}

// ---------------------------------------------------------------------------
// launch
// ---------------------------------------------------------------------------
extern "C" void kernel_launch(void* const* d_in, const int* in_sizes, int n_in,
                              void* d_out, int out_size) {
    const float* x  = (const float*)d_in[0];
    const int*   ei = (const int*)d_in[1];
    const float* ew = (const float*)d_in[2];
    const float* W1 = (const float*)d_in[3];
    const float* b1 = (const float*)d_in[4];
    const float* W2 = (const float*)d_in[5];
    const float* b2 = (const float*)d_in[6];
    float* out = (float*)d_out;

    int N = in_sizes[0] / DDIM;   // 50000
    int E = in_sizes[2];          // 800000
    const int* row = ei;
    const int* col = ei + E;

    int n4 = N * (DDIM / 4);

    deg_init_kernel<<<(N + 255) / 256, 256>>>(N);
    deg_acc_kernel<<<(E + 255) / 256, 256>>>(col, ew, E);
    dinv_kernel<<<(N + 255) / 256, 256>>>(N);

    dim3 ggrid(DDIM / BN, (N + BM - 1) / BM);

    // ---- layer 1 ----
    gemm_kernel<<<ggrid, 256>>>(x, W1, N, 0);
    init_agg_kernel<<<(n4 + 255) / 256, 256>>>(b1, N);
    scatter_kernel<<<(E + 3) / 4, 256>>>(row, col, ew, E);
    relu_kernel<<<(n4 + 255) / 256, 256>>>(out, N, 0);

    // ---- layer 2 ----
    gemm_kernel<<<ggrid, 256>>>(x, W2, N, 1);
    init_agg_kernel<<<(n4 + 255) / 256, 256>>>(b2, N);
    scatter_kernel<<<(E + 3) / 4, 256>>>(row, col, ew, E);
    relu_kernel<<<(n4 + 255) / 256, 256>>>(out, N, 1);
}

// round 6
// speedup vs baseline: 3.0406x; 2.5999x over previous
#include <cuda_runtime.h>
#include <cuda_bf16.h>

#define NMAX 50000
#define EMAX 800000
#define DDIM 256

// Scratch (device globals — no allocations allowed)
__device__ __align__(256) float g_h[NMAX * DDIM];   // h = A @ W (per layer)
__device__ __align__(256) float g_z[NMAX * DDIM];   // layer-1 output
__device__ __align__(256) float g_deg[NMAX];        // degree -> rsqrt(deg)
__device__ int   g_count[NMAX];                     // in-degree (edge count per col)
__device__ int   g_cursor[NMAX];                    // fill cursors
__device__ int   g_start[NMAX + 1];                 // CSR segment starts
__device__ int   g_esrc[EMAX];                      // src node per edge, sorted by col
__device__ float g_enorm[EMAX];                     // norm per edge, sorted by col

// ---------------------------------------------------------------------------
// degree + CSR count init
// ---------------------------------------------------------------------------
__global__ void deg_init_kernel(int N) {
    int i = blockIdx.x * blockDim.x + threadIdx.x;
    if (i < N) { g_deg[i] = 1.0f; g_count[i] = 0; g_cursor[i] = 0; }
}

__global__ void deg_acc_kernel(const int* __restrict__ col,
                               const float* __restrict__ ew, int E) {
    int e = blockIdx.x * blockDim.x + threadIdx.x;
    if (e < E) {
        int c = col[e];
        atomicAdd(&g_deg[c], ew[e]);
        atomicAdd(&g_count[c], 1);
    }
}

__global__ void dinv_kernel(int N) {
    int i = blockIdx.x * blockDim.x + threadIdx.x;
    if (i < N) g_deg[i] = rsqrtf(g_deg[i]);
}

// ---------------------------------------------------------------------------
// exclusive scan of g_count -> g_start  (single block, 1024 threads)
// ---------------------------------------------------------------------------
__global__ __launch_bounds__(1024) void scan_kernel(int N) {
    const int T = 1024;
    int tid = threadIdx.x;
    int chunk = (N + T - 1) / T;
    int begin = min(tid * chunk, N);
    int end = min(begin + chunk, N);

    int s = 0;
    for (int i = begin; i < end; i++) s += g_count[i];

    __shared__ int sums[T];
    sums[tid] = s;
    __syncthreads();

    // Hillis-Steele inclusive scan
    for (int d = 1; d < T; d <<= 1) {
        int v = (tid >= d) ? sums[tid - d] : 0;
        __syncthreads();
        sums[tid] += v;
        __syncthreads();
    }
    int off = sums[tid] - s;  // exclusive prefix

    for (int i = begin; i < end; i++) {
        g_start[i] = off;
        off += g_count[i];
    }
    if (tid == T - 1) g_start[N] = off;  // grand total = E
}

// ---------------------------------------------------------------------------
// CSR fill: place (src, norm) at start[col] + cursor[col]++
// ---------------------------------------------------------------------------
__global__ void fill_kernel(const int* __restrict__ row,
                            const int* __restrict__ col,
                            const float* __restrict__ ew, int E) {
    int e = blockIdx.x * blockDim.x + threadIdx.x;
    if (e >= E) return;
    int r = row[e];
    int c = col[e];
    int pos = atomicAdd(&g_cursor[c], 1);
    int idx = g_start[c] + pos;
    if (idx < 0 || idx >= EMAX) return;  // defensive: cannot trigger on spec shapes
    g_esrc[idx] = r;
    g_enorm[idx] = g_deg[r] * ew[e] * g_deg[c];
}

// ---------------------------------------------------------------------------
// GEMM: g_h[M,256] = A[M,256] @ W[256,256], FP32
// 128x128x8 tile, 256 threads, 8x8 per thread (2x(4+4) split), reg prefetch.
// ---------------------------------------------------------------------------
#define BM 128
#define BN 128
#define BK 8

__global__ __launch_bounds__(256) void gemm_kernel(const float* __restrict__ x_in,
                                                   const float* __restrict__ W,
                                                   int M, int layer) {
    const float* __restrict__ A = (layer == 0) ? x_in : (const float*)g_z;

    __shared__ float As[BK][BM];
    __shared__ float Bs[BK][BN];

    int tid = threadIdx.x;
    int tx = tid & 15;
    int ty = tid >> 4;

    int rowBase = blockIdx.y * BM;
    int colBase = blockIdx.x * BN;

    int arow = tid >> 1;
    int acol = (tid & 1) * 4;
    int brow = tid >> 5;
    int bcol = (tid & 31) * 4;

    int gm = rowBase + arow;
    bool aok = (gm < M);

    float4 aReg = aok ? *(const float4*)&A[(size_t)gm * DDIM + acol]
                      : make_float4(0.f, 0.f, 0.f, 0.f);
    float4 bReg = *(const float4*)&W[(size_t)brow * DDIM + colBase + bcol];

    float acc[8][8];
#pragma unroll
    for (int i = 0; i < 8; i++)
#pragma unroll
        for (int j = 0; j < 8; j++) acc[i][j] = 0.f;

    float af[8], bf[8];

    for (int k0 = 0; k0 < DDIM; k0 += BK) {
        As[acol + 0][arow] = aReg.x;
        As[acol + 1][arow] = aReg.y;
        As[acol + 2][arow] = aReg.z;
        As[acol + 3][arow] = aReg.w;
        *(float4*)&Bs[brow][bcol] = bReg;
        __syncthreads();

        if (k0 + BK < DDIM) {
            aReg = aok ? *(const float4*)&A[(size_t)gm * DDIM + k0 + BK + acol]
                       : make_float4(0.f, 0.f, 0.f, 0.f);
            bReg = *(const float4*)&W[(size_t)(k0 + BK + brow) * DDIM + colBase + bcol];
        }

#pragma unroll
        for (int kk = 0; kk < BK; kk++) {
            *(float4*)&af[0] = *(const float4*)&As[kk][ty * 4];
            *(float4*)&af[4] = *(const float4*)&As[kk][ty * 4 + 64];
            *(float4*)&bf[0] = *(const float4*)&Bs[kk][tx * 4];
            *(float4*)&bf[4] = *(const float4*)&Bs[kk][tx * 4 + 64];
#pragma unroll
            for (int i = 0; i < 8; i++)
#pragma unroll
                for (int j = 0; j < 8; j++) acc[i][j] += af[i] * bf[j];
        }
        __syncthreads();
    }

#pragma unroll
    for (int ih = 0; ih < 2; ih++) {
#pragma unroll
        for (int i = 0; i < 4; i++) {
            int m = rowBase + ty * 4 + ih * 64 + i;
            if (m < M) {
                int r = ih * 4 + i;
                *(float4*)&g_h[(size_t)m * DDIM + colBase + tx * 4] =
                    make_float4(acc[r][0], acc[r][1], acc[r][2], acc[r][3]);
                *(float4*)&g_h[(size_t)m * DDIM + colBase + tx * 4 + 64] =
                    make_float4(acc[r][4], acc[r][5], acc[r][6], acc[r][7]);
            }
        }
    }
}

// ---------------------------------------------------------------------------
// Fused gather + self-loop + bias + ReLU (no atomics):
// dst[n] = relu( sum_{e in CSR[n]} norm_e * h[src_e] + dinv[n]^2 * h[n] + b )
// 64 threads per node (float4 lanes over D=256), 4 nodes per 256-thread block.
// ---------------------------------------------------------------------------
__global__ __launch_bounds__(256) void gather_kernel(const float* __restrict__ b,
                                                     float* __restrict__ out,
                                                     int N, int layer) {
    int node = blockIdx.x * 4 + (threadIdx.x >> 6);
    int lane = threadIdx.x & 63;
    if (node >= N) return;

    int s0 = g_start[node];
    int s1 = g_start[node + 1];

    float4 acc = make_float4(0.f, 0.f, 0.f, 0.f);

    int j = s0;
    for (; j + 1 < s1; j += 2) {
        int src0 = g_esrc[j];
        int src1 = g_esrc[j + 1];
        float w0 = g_enorm[j];
        float w1 = g_enorm[j + 1];
        float4 v0 = ((const float4*)(g_h + (size_t)src0 * DDIM))[lane];
        float4 v1 = ((const float4*)(g_h + (size_t)src1 * DDIM))[lane];
        acc.x += w0 * v0.x + w1 * v1.x;
        acc.y += w0 * v0.y + w1 * v1.y;
        acc.z += w0 * v0.z + w1 * v1.z;
        acc.w += w0 * v0.w + w1 * v1.w;
    }
    if (j < s1) {
        int src = g_esrc[j];
        float w = g_enorm[j];
        float4 v = ((const float4*)(g_h + (size_t)src * DDIM))[lane];
        acc.x += w * v.x;
        acc.y += w * v.y;
        acc.z += w * v.z;
        acc.w += w * v.w;
    }

    float di = g_deg[node];
    float s = di * di;
    float4 h = ((const float4*)(g_h + (size_t)node * DDIM))[lane];
    float4 bb = ((const float4*)b)[lane];

    float4 o;
    o.x = fmaxf(acc.x + s * h.x + bb.x, 0.f);
    o.y = fmaxf(acc.y + s * h.y + bb.y, 0.f);
    o.z = fmaxf(acc.z + s * h.z + bb.z, 0.f);
    o.w = fmaxf(acc.w + s * h.w + bb.w, 0.f);

    float4* dst = (layer == 0) ? (float4*)g_z : (float4*)out;
    dst[(size_t)node * (DDIM / 4) + lane] = o;
}

// ---------------------------------------------------------------------------
// launch
// ---------------------------------------------------------------------------
extern "C" void kernel_launch(void* const* d_in, const int* in_sizes, int n_in,
                              void* d_out, int out_size) {
    const float* x  = (const float*)d_in[0];
    const int*   ei = (const int*)d_in[1];
    const float* ew = (const float*)d_in[2];
    const float* W1 = (const float*)d_in[3];
    const float* b1 = (const float*)d_in[4];
    const float* W2 = (const float*)d_in[5];
    const float* b2 = (const float*)d_in[6];
    float* out = (float*)d_out;

    int N = in_sizes[0] / DDIM;   // 50000
    int E = in_sizes[2];          // 800000
    if (N > NMAX) N = NMAX;       // defensive; no-ops on spec shapes
    if (E > EMAX) E = EMAX;
    const int* row = ei;
    const int* col = ei + E;

    // degree + CSR (shared by both layers)
    deg_init_kernel<<<(N + 255) / 256, 256>>>(N);
    deg_acc_kernel<<<(E + 255) / 256, 256>>>(col, ew, E);
    dinv_kernel<<<(N + 255) / 256, 256>>>(N);
    scan_kernel<<<1, 1024>>>(N);
    fill_kernel<<<(E + 255) / 256, 256>>>(row, col, ew, E);

    dim3 ggrid(DDIM / BN, (N + BM - 1) / BM);
    int ngrid = (N + 3) / 4;

    // ---- layer 1 ----
    gemm_kernel<<<ggrid, 256>>>(x, W1, N, 0);
    gather_kernel<<<ngrid, 256>>>(b1, out, N, 0);

    // ---- layer 2 ----
    gemm_kernel<<<ggrid, 256>>>(x, W2, N, 1);
    gather_kernel<<<ngrid, 256>>>(b2, out, N, 1);
}

// round 9
// speedup vs baseline: 3.2948x; 1.0836x over previous
#include <cuda_runtime.h>
#include <cuda_bf16.h>

#define NMAX 50000
#define EMAX 800000
#define DDIM 256
#define SCAN_B 256  // scan block width

// Scratch (device globals — no allocations allowed)
__device__ __align__(256) float g_h[NMAX * DDIM];   // h = A @ W (per layer)
__device__ __align__(256) float g_z[NMAX * DDIM];   // layer-1 output
__device__ __align__(256) float g_deg[NMAX];        // degree -> rsqrt(deg)
__device__ int   g_count[NMAX];                     // in-degree per col
__device__ int   g_cursor[NMAX];                    // fill cursors
__device__ int   g_start[NMAX + 1];                 // CSR segment starts
__device__ int   g_bsum[(NMAX + SCAN_B - 1) / SCAN_B];   // block sums
__device__ int   g_boff[(NMAX + SCAN_B - 1) / SCAN_B];   // block offsets
__device__ int   g_esrc[EMAX];                      // src node per edge (col-sorted)
__device__ float g_enorm[EMAX];                     // norm per edge (col-sorted)

// ---------------------------------------------------------------------------
// degree + CSR count init
// ---------------------------------------------------------------------------
__global__ void deg_init_kernel(int N) {
    int i = blockIdx.x * blockDim.x + threadIdx.x;
    if (i < N) { g_deg[i] = 1.0f; g_count[i] = 0; g_cursor[i] = 0; }
}

__global__ void deg_acc_kernel(const int* __restrict__ col,
                               const float* __restrict__ ew, int E) {
    int e = blockIdx.x * blockDim.x + threadIdx.x;
    if (e < E) {
        int c = col[e];
        atomicAdd(&g_deg[c], ew[e]);
        atomicAdd(&g_count[c], 1);
    }
}

__global__ void dinv_kernel(int N) {
    int i = blockIdx.x * blockDim.x + threadIdx.x;
    if (i < N) g_deg[i] = rsqrtf(g_deg[i]);
}

// ---------------------------------------------------------------------------
// 3-phase exclusive scan of g_count -> g_start
// ---------------------------------------------------------------------------
__global__ __launch_bounds__(SCAN_B) void scan1_kernel(int N) {
    int tid = threadIdx.x;
    int i = blockIdx.x * SCAN_B + tid;
    int v = (i < N) ? g_count[i] : 0;

    __shared__ int sh[SCAN_B];
    sh[tid] = v;
    __syncthreads();
    for (int d = 1; d < SCAN_B; d <<= 1) {
        int t = (tid >= d) ? sh[tid - d] : 0;
        __syncthreads();
        sh[tid] += t;
        __syncthreads();
    }
    if (i < N) g_start[i] = sh[tid] - v;           // exclusive within block
    if (tid == SCAN_B - 1) g_bsum[blockIdx.x] = sh[tid];
}

__global__ __launch_bounds__(SCAN_B) void scan2_kernel(int nb) {
    int tid = threadIdx.x;
    int v = (tid < nb) ? g_bsum[tid] : 0;
    __shared__ int sh[SCAN_B];
    sh[tid] = v;
    __syncthreads();
    for (int d = 1; d < SCAN_B; d <<= 1) {
        int t = (tid >= d) ? sh[tid - d] : 0;
        __syncthreads();
        sh[tid] += t;
        __syncthreads();
    }
    if (tid < nb) g_boff[tid] = sh[tid] - v;       // exclusive block offsets
}

__global__ __launch_bounds__(SCAN_B) void scan3_kernel(int N, int E) {
    int i = blockIdx.x * SCAN_B + threadIdx.x;
    if (i < N) g_start[i] += g_boff[blockIdx.x];
    if (i == 0) g_start[N] = E;                    // grand total known analytically
}

// ---------------------------------------------------------------------------
// CSR fill: place (src, norm) at start[col] + cursor[col]++
// ---------------------------------------------------------------------------
__global__ void fill_kernel(const int* __restrict__ row,
                            const int* __restrict__ col,
                            const float* __restrict__ ew, int E) {
    int e = blockIdx.x * blockDim.x + threadIdx.x;
    if (e >= E) return;
    int r = row[e];
    int c = col[e];
    int pos = atomicAdd(&g_cursor[c], 1);
    int idx = g_start[c] + pos;
    if (idx < 0 || idx >= EMAX) return;  // defensive
    g_esrc[idx] = r;
    g_enorm[idx] = g_deg[r] * ew[e] * g_deg[c];
}

// ---------------------------------------------------------------------------
// GEMM: g_h[M,256] = A[M,256] @ W[256,256], FP32   (R6-proven version)
// 128x128x8 tile, 256 threads, 8x8 per thread, reg prefetch, single buffer.
// ---------------------------------------------------------------------------
#define BM 128
#define BN 128
#define BK 8

__global__ __launch_bounds__(256) void gemm_kernel(const float* __restrict__ x_in,
                                                   const float* __restrict__ W,
                                                   int M, int layer) {
    const float* __restrict__ A = (layer == 0) ? x_in : (const float*)g_z;

    __shared__ float As[BK][BM];
    __shared__ float Bs[BK][BN];

    int tid = threadIdx.x;
    int tx = tid & 15;
    int ty = tid >> 4;

    int rowBase = blockIdx.y * BM;
    int colBase = blockIdx.x * BN;

    int arow = tid >> 1;
    int acol = (tid & 1) * 4;
    int brow = tid >> 5;
    int bcol = (tid & 31) * 4;

    int gm = rowBase + arow;
    bool aok = (gm < M);

    float4 aReg = aok ? *(const float4*)&A[(size_t)gm * DDIM + acol]
                      : make_float4(0.f, 0.f, 0.f, 0.f);
    float4 bReg = *(const float4*)&W[(size_t)brow * DDIM + colBase + bcol];

    float acc[8][8];
#pragma unroll
    for (int i = 0; i < 8; i++)
#pragma unroll
        for (int j = 0; j < 8; j++) acc[i][j] = 0.f;

    float af[8], bf[8];

    for (int k0 = 0; k0 < DDIM; k0 += BK) {
        As[acol + 0][arow] = aReg.x;
        As[acol + 1][arow] = aReg.y;
        As[acol + 2][arow] = aReg.z;
        As[acol + 3][arow] = aReg.w;
        *(float4*)&Bs[brow][bcol] = bReg;
        __syncthreads();

        if (k0 + BK < DDIM) {
            aReg = aok ? *(const float4*)&A[(size_t)gm * DDIM + k0 + BK + acol]
                       : make_float4(0.f, 0.f, 0.f, 0.f);
            bReg = *(const float4*)&W[(size_t)(k0 + BK + brow) * DDIM + colBase + bcol];
        }

#pragma unroll
        for (int kk = 0; kk < BK; kk++) {
            *(float4*)&af[0] = *(const float4*)&As[kk][ty * 4];
            *(float4*)&af[4] = *(const float4*)&As[kk][ty * 4 + 64];
            *(float4*)&bf[0] = *(const float4*)&Bs[kk][tx * 4];
            *(float4*)&bf[4] = *(const float4*)&Bs[kk][tx * 4 + 64];
#pragma unroll
            for (int i = 0; i < 8; i++)
#pragma unroll
                for (int j = 0; j < 8; j++) acc[i][j] += af[i] * bf[j];
        }
        __syncthreads();
    }

#pragma unroll
    for (int ih = 0; ih < 2; ih++) {
#pragma unroll
        for (int i = 0; i < 4; i++) {
            int m = rowBase + ty * 4 + ih * 64 + i;
            if (m < M) {
                int r = ih * 4 + i;
                *(float4*)&g_h[(size_t)m * DDIM + colBase + tx * 4] =
                    make_float4(acc[r][0], acc[r][1], acc[r][2], acc[r][3]);
                *(float4*)&g_h[(size_t)m * DDIM + colBase + tx * 4 + 64] =
                    make_float4(acc[r][4], acc[r][5], acc[r][6], acc[r][7]);
            }
        }
    }
}

// ---------------------------------------------------------------------------
// Fused gather + self-loop + bias + ReLU (no atomics)
// ---------------------------------------------------------------------------
__global__ __launch_bounds__(256) void gather_kernel(const float* __restrict__ b,
                                                     float* __restrict__ out,
                                                     int N, int layer) {
    int node = blockIdx.x * 4 + (threadIdx.x >> 6);
    int lane = threadIdx.x & 63;
    if (node >= N) return;

    int s0 = g_start[node];
    int s1 = g_start[node + 1];

    float4 acc = make_float4(0.f, 0.f, 0.f, 0.f);

    int j = s0;
    for (; j + 1 < s1; j += 2) {
        int src0 = g_esrc[j];
        int src1 = g_esrc[j + 1];
        float w0 = g_enorm[j];
        float w1 = g_enorm[j + 1];
        float4 v0 = ((const float4*)(g_h + (size_t)src0 * DDIM))[lane];
        float4 v1 = ((const float4*)(g_h + (size_t)src1 * DDIM))[lane];
        acc.x += w0 * v0.x + w1 * v1.x;
        acc.y += w0 * v0.y + w1 * v1.y;
        acc.z += w0 * v0.z + w1 * v1.z;
        acc.w += w0 * v0.w + w1 * v1.w;
    }
    if (j < s1) {
        int src = g_esrc[j];
        float w = g_enorm[j];
        float4 v = ((const float4*)(g_h + (size_t)src * DDIM))[lane];
        acc.x += w * v.x;
        acc.y += w * v.y;
        acc.z += w * v.z;
        acc.w += w * v.w;
    }

    float di = g_deg[node];
    float s = di * di;
    float4 h = ((const float4*)(g_h + (size_t)node * DDIM))[lane];
    float4 bb = ((const float4*)b)[lane];

    float4 o;
    o.x = fmaxf(acc.x + s * h.x + bb.x, 0.f);
    o.y = fmaxf(acc.y + s * h.y + bb.y, 0.f);
    o.z = fmaxf(acc.z + s * h.z + bb.z, 0.f);
    o.w = fmaxf(acc.w + s * h.w + bb.w, 0.f);

    float4* dst = (layer == 0) ? (float4*)g_z : (float4*)out;
    dst[(size_t)node * (DDIM / 4) + lane] = o;
}

// ---------------------------------------------------------------------------
// launch
// ---------------------------------------------------------------------------
extern "C" void kernel_launch(void* const* d_in, const int* in_sizes, int n_in,
                              void* d_out, int out_size) {
    const float* x  = (const float*)d_in[0];
    const int*   ei = (const int*)d_in[1];
    const float* ew = (const float*)d_in[2];
    const float* W1 = (const float*)d_in[3];
    const float* b1 = (const float*)d_in[4];
    const float* W2 = (const float*)d_in[5];
    const float* b2 = (const float*)d_in[6];
    float* out = (float*)d_out;

    int N = in_sizes[0] / DDIM;   // 50000
    int E = in_sizes[2];          // 800000
    if (N > NMAX) N = NMAX;
    if (E > EMAX) E = EMAX;
    const int* row = ei;
    const int* col = ei + E;

    int nb = (N + SCAN_B - 1) / SCAN_B;  // 196

    // degree + CSR (shared by both layers)
    deg_init_kernel<<<(N + 255) / 256, 256>>>(N);
    deg_acc_kernel<<<(E + 255) / 256, 256>>>(col, ew, E);
    dinv_kernel<<<(N + 255) / 256, 256>>>(N);
    scan1_kernel<<<nb, SCAN_B>>>(N);
    scan2_kernel<<<1, SCAN_B>>>(nb);
    scan3_kernel<<<nb, SCAN_B>>>(N, E);
    fill_kernel<<<(E + 255) / 256, 256>>>(row, col, ew, E);

    dim3 ggrid(DDIM / BN, (N + BM - 1) / BM);
    int ngrid = (N + 3) / 4;

    // ---- layer 1 ----
    gemm_kernel<<<ggrid, 256>>>(x, W1, N, 0);
    gather_kernel<<<ngrid, 256>>>(b1, out, N, 0);

    // ---- layer 2 ----
    gemm_kernel<<<ggrid, 256>>>(x, W2, N, 1);
    gather_kernel<<<ngrid, 256>>>(b2, out, N, 1);
}